// round 5
// baseline (speedup 1.0000x reference)
#include <cuda_runtime.h>
#include <math.h>

#define BATCH   8
#define NPTS    8192
#define NPOINT  2048
#define NSAMPLE 32
#define NGRP    256     // groups of 32 sorted points
#define FULLM   0xffffffffu

// ---------------- device scratch (no allocs allowed) ----------------
__device__ float g_W1t[3 * 64];
__device__ float g_W2t[64 * 64];
__device__ float g_W3t[64 * 128];
__device__ float g_B[256];

// ---------------- prep: fold BN into weights ----------------
__global__ void prep_kernel(
    const float* __restrict__ w1, const float* __restrict__ b1, const float* __restrict__ g1,
    const float* __restrict__ be1, const float* __restrict__ m1, const float* __restrict__ v1,
    const float* __restrict__ w2, const float* __restrict__ b2, const float* __restrict__ g2,
    const float* __restrict__ be2, const float* __restrict__ m2, const float* __restrict__ v2,
    const float* __restrict__ w3, const float* __restrict__ b3, const float* __restrict__ g3,
    const float* __restrict__ be3, const float* __restrict__ m3, const float* __restrict__ v3)
{
    int t = threadIdx.x;
    if (t < 64) {
        float s1 = g1[t] / sqrtf(v1[t] + 1e-5f);
        g_B[t] = (b1[t] - m1[t]) * s1 + be1[t];
        for (int c = 0; c < 3; c++) g_W1t[c * 64 + t] = w1[t * 3 + c] * s1;
        float s2 = g2[t] / sqrtf(v2[t] + 1e-5f);
        g_B[64 + t] = (b2[t] - m2[t]) * s2 + be2[t];
        for (int c = 0; c < 64; c++) g_W2t[c * 64 + t] = w2[t * 64 + c] * s2;
    }
    if (t < 128) {
        float s3 = g3[t] / sqrtf(v3[t] + 1e-5f);
        g_B[128 + t] = (b3[t] - m3[t]) * s3 + be3[t];
        for (int c = 0; c < 64; c++) g_W3t[c * 128 + t] = w3[t * 64 + c] * s3;
    }
}

// ---------------- FPS: Morton sort + single-warp lazy loop ----------------
// transposed addr for sorted position s: a = (s&31)*256 + (s>>5)
extern __shared__ float fps_sm[];

__device__ __forceinline__ unsigned spread3(unsigned v) {
    v = (v | (v << 4)) & 0x0C3u;
    v = (v | (v << 2)) & 0x249u;
    return v;
}

__global__ __launch_bounds__(1024, 1) void fps_kernel(
    const float* __restrict__ xyz, float* __restrict__ newxyz)
{
    const int b = blockIdx.x;
    const float* P = xyz + (size_t)b * NPTS * 3;
    float* O = newxyz + (size_t)b * NPOINT * 3;
    const int tid = threadIdx.x;
    const int lane = tid & 31, wid = tid >> 5;

    float* sxs = fps_sm;                    // [8192] transposed
    float* sys = sxs + NPTS;
    float* szs = sys + NPTS;
    float* dds = szs + NPTS;                // [8192] transposed
    int*   ordt = (int*)(dds + NPTS);       // [8192] transposed (orig index)
    int*   hist = ordt + NPTS;              // [4096]
    float* gvx  = (float*)(hist + 4096);    // [256] group vmax
    unsigned* giv = (unsigned*)(gvx + NGRP);// [256] group tie-min orig idx
    float* gxl = (float*)(giv + NGRP);      // 6 x [256] group bbox
    float* gxh = gxl + NGRP;
    float* gyl = gxh + NGRP;
    float* gyh = gyl + NGRP;
    float* gzl = gyh + NGRP;
    float* gzh = gzl + NGRP;
    unsigned short* inv = (unsigned short*)(gzh + NGRP);  // [8192] orig -> sorted pos

    __shared__ int wsums[32];

    // ---- load + Morton keys ----
    float xr[8], yr[8], zr[8];
    unsigned key[8];
#pragma unroll
    for (int k = 0; k < 8; k++) {
        int p = tid + 1024 * k;
        float x = P[3 * p], y = P[3 * p + 1], z = P[3 * p + 2];
        xr[k] = x; yr[k] = y; zr[k] = z;
        int ix = min(15, max(0, (int)(x * 16.0f)));
        int iy = min(15, max(0, (int)(y * 16.0f)));
        int iz = min(15, max(0, (int)(z * 16.0f)));
        key[k] = spread3((unsigned)ix) | (spread3((unsigned)iy) << 1) | (spread3((unsigned)iz) << 2);
    }
    for (int i = tid; i < 4096; i += 1024) hist[i] = 0;
    __syncthreads();
#pragma unroll
    for (int k = 0; k < 8; k++) atomicAdd(&hist[key[k]], 1);
    __syncthreads();

    // ---- exclusive scan over 4096 bins ----
    int h0 = hist[4 * tid], h1 = hist[4 * tid + 1], h2 = hist[4 * tid + 2], h3 = hist[4 * tid + 3];
    int tsum = h0 + h1 + h2 + h3;
    int inc = tsum;
#pragma unroll
    for (int off = 1; off < 32; off <<= 1) {
        int n = __shfl_up_sync(FULLM, inc, off);
        if (lane >= off) inc += n;
    }
    if (lane == 31) wsums[wid] = inc;
    __syncthreads();
    if (wid == 0) {
        int s = wsums[lane];
        int i2 = s;
#pragma unroll
        for (int off = 1; off < 32; off <<= 1) {
            int n = __shfl_up_sync(FULLM, i2, off);
            if (lane >= off) i2 += n;
        }
        wsums[lane] = i2 - s;
    }
    __syncthreads();
    {
        int run = wsums[wid] + (inc - tsum);
        hist[4 * tid] = run; run += h0;
        hist[4 * tid + 1] = run; run += h1;
        hist[4 * tid + 2] = run; run += h2;
        hist[4 * tid + 3] = run;
    }
    __syncthreads();

    // ---- scatter into transposed sorted layout ----
#pragma unroll
    for (int k = 0; k < 8; k++) {
        int orig = tid + 1024 * k;
        int s = atomicAdd(&hist[key[k]], 1);
        int a = ((s & 31) << 8) | (s >> 5);
        sxs[a] = xr[k]; sys[a] = yr[k]; szs[a] = zr[k];
        ordt[a] = orig;
        inv[orig] = (unsigned short)s;
    }
    __syncthreads();

    // ---- init dists vs P[0] (exact rn) ----
    float c0x = P[0], c0y = P[1], c0z = P[2];
    if (tid == 0) { O[0] = c0x; O[1] = c0y; O[2] = c0z; }
#pragma unroll
    for (int k = 0; k < 8; k++) {
        int a = tid + 1024 * k;
        float dx = __fadd_rn(sxs[a], -c0x);
        float dy = __fadd_rn(sys[a], -c0y);
        float dz = __fadd_rn(szs[a], -c0z);
        dds[a] = __fadd_rn(__fadd_rn(__fmul_rn(dx, dx), __fmul_rn(dy, dy)), __fmul_rn(dz, dz));
    }
    __syncthreads();

    // ---- per-group caches: bbox + vmax + tie-min orig index ----
    if (tid < NGRP) {
        int g = tid;
        float bxl = 1e30f, bxh = -1e30f, byl = 1e30f, byh = -1e30f, bzl = 1e30f, bzh = -1e30f;
        float v = -1.0f; unsigned bi = 0;
        for (int j = 0; j < 32; j++) {
            int a = j * 256 + g;
            float x = sxs[a], y = sys[a], z = szs[a];
            bxl = fminf(bxl, x); bxh = fmaxf(bxh, x);
            byl = fminf(byl, y); byh = fmaxf(byh, y);
            bzl = fminf(bzl, z); bzh = fmaxf(bzh, z);
            float dv = dds[a]; unsigned o = (unsigned)ordt[a];
            if (dv > v) { v = dv; bi = o; }
            else if (dv == v) bi = min(bi, o);
        }
        gvx[g] = v; giv[g] = bi;
        gxl[g] = bxl; gxh[g] = bxh; gyl[g] = byl; gyh[g] = byh; gzl[g] = bzl; gzh[g] = bzh;
    }
    __syncthreads();

    if (wid != 0) return;   // single-warp driver from here on

    // ---- thread cache: union bbox + (vmax, tie idx) over my 8 groups ----
    const int l = lane;
    float bxl = 1e30f, bxh = -1e30f, byl = 1e30f, byh = -1e30f, bzl = 1e30f, bzh = -1e30f;
#pragma unroll
    for (int k = 0; k < 8; k++) {
        int g = 8 * l + k;
        bxl = fminf(bxl, gxl[g]); bxh = fmaxf(bxh, gxh[g]);
        byl = fminf(byl, gyl[g]); byh = fmaxf(byh, gyh[g]);
        bzl = fminf(bzl, gzl[g]); bzh = fmaxf(bzh, gzh[g]);
    }
    const float bcx = (bxl + bxh) * 0.5f, bex = (bxh - bxl) * 0.5f;
    const float bcy = (byl + byh) * 0.5f, bey = (byh - byl) * 0.5f;
    const float bcz = (bzl + bzh) * 0.5f, bez = (bzh - bzl) * 0.5f;

    float vth = -1.0f; unsigned bth = 0;
#pragma unroll
    for (int k = 0; k < 8; k++) {
        int g = 8 * l + k;
        float gv = gvx[g]; unsigned gi = giv[g];
        if (gv > vth) { vth = gv; bth = gi; }
        else if (gv == vth) bth = min(bth, gi);
    }

    float cx = c0x, cy = c0y, cz = c0z;

    for (int it = 1; it < NPOINT; ++it) {
        // ---- thread-level conservative skip ----
        float tx = fmaxf(fabsf(cx - bcx) - bex, 0.0f);
        float ty = fmaxf(fabsf(cy - bcy) - bey, 0.0f);
        float tz = fmaxf(fabsf(cz - bcz) - bez, 0.0f);
        float bound = tx * tx + ty * ty + tz * tz;
        if (bound < vth * 1.0002f) {
            bool any = false;
#pragma unroll 1
            for (int k = 0; k < 8; k++) {
                int g = 8 * l + k;
                float gx2 = fmaxf(fabsf(cx - (gxl[g] + gxh[g]) * 0.5f) - (gxh[g] - gxl[g]) * 0.5f, 0.0f);
                float gy2 = fmaxf(fabsf(cy - (gyl[g] + gyh[g]) * 0.5f) - (gyh[g] - gyl[g]) * 0.5f, 0.0f);
                float gz2 = fmaxf(fabsf(cz - (gzl[g] + gzh[g]) * 0.5f) - (gzh[g] - gzl[g]) * 0.5f, 0.0f);
                float gb = gx2 * gx2 + gy2 * gy2 + gz2 * gz2;
                float gvmax = gvx[g];
                if (gb < gvmax * 1.0002f) {
                    float v = -1.0f; unsigned bi = 0;
#pragma unroll 1
                    for (int j = 0; j < 32; j++) {
                        int a = j * 256 + g;
                        float dx = __fadd_rn(sxs[a], -cx);
                        float dy = __fadd_rn(sys[a], -cy);
                        float dz = __fadd_rn(szs[a], -cz);
                        float s = __fadd_rn(__fadd_rn(__fmul_rn(dx, dx), __fmul_rn(dy, dy)),
                                            __fmul_rn(dz, dz));
                        float dn = fminf(dds[a], s);
                        dds[a] = dn;
                        unsigned o = (unsigned)ordt[a];
                        if (dn > v) { v = dn; bi = o; }
                        else if (dn == v) bi = min(bi, o);
                    }
                    gvx[g] = v; giv[g] = bi;
                    any = true;
                }
            }
            if (any) {
                float v = -1.0f; unsigned bi = 0;
#pragma unroll
                for (int k = 0; k < 8; k++) {
                    int g = 8 * l + k;
                    float gv = gvx[g]; unsigned gi = giv[g];
                    if (gv > v) { v = gv; bi = gi; }
                    else if (gv == v) bi = min(bi, gi);
                }
                vth = v; bth = bi;
            }
        }

        // ---- warp argmax (exact tie-break: max value, min orig index) ----
        unsigned keyv = __float_as_uint(vth);           // d >= 0
        unsigned wmax = __reduce_max_sync(FULLM, keyv);
        unsigned cand = (keyv == wmax) ? bth : FULLM;
        unsigned ci   = __reduce_min_sync(FULLM, cand); // orig index of pick

        int s = (int)inv[ci];
        int a = ((s & 31) << 8) | (s >> 5);
        cx = sxs[a]; cy = sys[a]; cz = szs[a];
        if (l == 0) { float* o = O + 3 * it; o[0] = cx; o[1] = cy; o[2] = cz; }
    }
}

// ---------------- fused ball-query + MLP + maxpool (unchanged) ----------------
extern __shared__ float fus_sm[];

__global__ __launch_bounds__(256) void fused_kernel(
    const float* __restrict__ xyz, const float* __restrict__ newxyz,
    float* __restrict__ out2)
{
    float* W2t   = fus_sm;
    float* W3t   = W2t + 64 * 64;
    float* W1t   = W3t + 64 * 128;
    float* Bsh   = W1t + 192;
    float* stage = Bsh + 256;
    int*   nb    = (int*)(stage + 128 * 8);

    const int tid = threadIdx.x;
    for (int i = tid; i < 64 * 64; i += 256)  W2t[i] = g_W2t[i];
    for (int i = tid; i < 64 * 128; i += 256) W3t[i] = g_W3t[i];
    if (tid < 192) W1t[tid] = g_W1t[tid];
    if (tid < 256) Bsh[tid] = g_B[tid];
    __syncthreads();

    const int w = tid >> 5, lane = tid & 31;
    const int b = blockIdx.x >> 8;
    const int m0 = (blockIdx.x & 255) * 8;
    const int m = m0 + w;

    const float* P = xyz + (size_t)b * NPTS * 3;
    const float* C = newxyz + ((size_t)b * NPOINT + m) * 3;
    const float cx = C[0], cy = C[1], cz = C[2];

    const float R2 = (float)(0.2 * 0.2);
    int* mynb = nb + w * 32;
    int cnt = 0;
    for (int base = 0; base < NPTS && cnt < NSAMPLE; base += 32) {
        int p = base + lane;
        float x = P[3 * p], y = P[3 * p + 1], z = P[3 * p + 2];
        float dx = __fadd_rn(x, -cx), dy = __fadd_rn(y, -cy), dz = __fadd_rn(z, -cz);
        float s = __fadd_rn(__fadd_rn(__fmul_rn(dx, dx), __fmul_rn(dy, dy)), __fmul_rn(dz, dz));
        bool in = (s <= R2);
        unsigned msk = __ballot_sync(FULLM, in);
        int pos = cnt + __popc(msk & ((1u << lane) - 1u));
        if (in && pos < NSAMPLE) mynb[pos] = p;
        cnt += __popc(msk);
    }
    __syncwarp();
    int src = (cnt >= NSAMPLE) ? lane : (lane % cnt);
    int g = mynb[src];

    float gx = P[3 * g] - cx, gy = P[3 * g + 1] - cy, gz = P[3 * g + 2] - cz;

    float h1[64];
#pragma unroll
    for (int o = 0; o < 64; o++) h1[o] = fmaf(gx, W1t[o], Bsh[o]);
#pragma unroll
    for (int o = 0; o < 64; o++) h1[o] = fmaf(gy, W1t[64 + o], h1[o]);
#pragma unroll
    for (int o = 0; o < 64; o++) h1[o] = fmaxf(fmaf(gz, W1t[128 + o], h1[o]), 0.0f);

    float h2[64];
#pragma unroll
    for (int o = 0; o < 64; o++) h2[o] = Bsh[64 + o];
#pragma unroll
    for (int c = 0; c < 64; c++) {
        float hc = h1[c];
        const float4* wr = (const float4*)(W2t + c * 64);
#pragma unroll
        for (int q = 0; q < 16; q++) {
            float4 wv = wr[q];
            h2[4 * q + 0] = fmaf(hc, wv.x, h2[4 * q + 0]);
            h2[4 * q + 1] = fmaf(hc, wv.y, h2[4 * q + 1]);
            h2[4 * q + 2] = fmaf(hc, wv.z, h2[4 * q + 2]);
            h2[4 * q + 3] = fmaf(hc, wv.w, h2[4 * q + 3]);
        }
    }
#pragma unroll
    for (int o = 0; o < 64; o++) h2[o] = fmaxf(h2[o], 0.0f);

#pragma unroll
    for (int half = 0; half < 2; half++) {
        float acc[64];
#pragma unroll
        for (int o = 0; o < 64; o++) acc[o] = Bsh[128 + half * 64 + o];
#pragma unroll
        for (int c = 0; c < 64; c++) {
            float hc = h2[c];
            const float4* wr = (const float4*)(W3t + c * 128 + half * 64);
#pragma unroll
            for (int q = 0; q < 16; q++) {
                float4 wv = wr[q];
                acc[4 * q + 0] = fmaf(hc, wv.x, acc[4 * q + 0]);
                acc[4 * q + 1] = fmaf(hc, wv.y, acc[4 * q + 1]);
                acc[4 * q + 2] = fmaf(hc, wv.z, acc[4 * q + 2]);
                acc[4 * q + 3] = fmaf(hc, wv.w, acc[4 * q + 3]);
            }
        }
#pragma unroll
        for (int o = 0; o < 64; o++) acc[o] = fmaxf(acc[o], 0.0f);
#pragma unroll
        for (int off = 16; off >= 1; off >>= 1) {
#pragma unroll
            for (int o = 0; o < 64; o++)
                acc[o] = fmaxf(acc[o], __shfl_down_sync(FULLM, acc[o], off));
        }
        if (lane == 0) {
#pragma unroll
            for (int o = 0; o < 64; o++) stage[(half * 64 + o) * 8 + w] = acc[o];
        }
    }
    __syncthreads();

    {
        int ch = tid >> 1, part = tid & 1;
        float4 v = ((const float4*)stage)[tid];
        *(float4*)(out2 + ((size_t)(b * 128 + ch)) * NPOINT + m0 + part * 4) = v;
    }
}

// ---------------- launch ----------------
extern "C" void kernel_launch(void* const* d_in, const int* in_sizes, int n_in,
                              void* d_out, int out_size)
{
    const float* xyz = (const float*)d_in[0];
    const float* w1 = (const float*)d_in[1];  const float* b1 = (const float*)d_in[2];
    const float* g1 = (const float*)d_in[3];  const float* be1 = (const float*)d_in[4];
    const float* m1 = (const float*)d_in[5];  const float* v1 = (const float*)d_in[6];
    const float* w2 = (const float*)d_in[7];  const float* b2 = (const float*)d_in[8];
    const float* g2 = (const float*)d_in[9];  const float* be2 = (const float*)d_in[10];
    const float* m2 = (const float*)d_in[11]; const float* v2 = (const float*)d_in[12];
    const float* w3 = (const float*)d_in[13]; const float* b3 = (const float*)d_in[14];
    const float* g3 = (const float*)d_in[15]; const float* be3 = (const float*)d_in[16];
    const float* m3 = (const float*)d_in[17]; const float* v3 = (const float*)d_in[18];

    float* out = (float*)d_out;
    float* newxyz = out;
    float* out2 = out + (size_t)BATCH * NPOINT * 3;

    // smem: 4*8192 (sx,sy,sz,dd) + 8192 (ordt) + 4096 (hist) + 8*256 (group) + 4096 (inv as floats)
    const int FPS_SMEM = (4 * NPTS + NPTS + 4096 + 8 * NGRP + NPTS / 2) * 4;  // 204800
    cudaFuncSetAttribute(fps_kernel, cudaFuncAttributeMaxDynamicSharedMemorySize, FPS_SMEM);
    cudaFuncSetAttribute(fused_kernel, cudaFuncAttributeMaxDynamicSharedMemorySize, 57344);

    prep_kernel<<<1, 128>>>(w1, b1, g1, be1, m1, v1,
                            w2, b2, g2, be2, m2, v2,
                            w3, b3, g3, be3, m3, v3);
    fps_kernel<<<BATCH, 1024, FPS_SMEM>>>(xyz, newxyz);
    fused_kernel<<<BATCH * (NPOINT / 8), 256, 56064>>>(xyz, newxyz, out2);
    (void)in_sizes; (void)n_in; (void)out_size;
}

// round 6
// speedup vs baseline: 5.0038x; 5.0038x over previous
#include <cuda_runtime.h>
#include <math.h>

#define BATCH   8
#define NPTS    8192
#define NPOINT  2048
#define NSAMPLE 32
#define FULLM   0xffffffffu

// ---------------- device scratch (no allocs allowed) ----------------
__device__ float g_W1t[3 * 64];
__device__ float g_W2t[64 * 64];
__device__ float g_W3t[64 * 128];
__device__ float g_B[256];

// ---------------- prep: fold BN into weights ----------------
__global__ void prep_kernel(
    const float* __restrict__ w1, const float* __restrict__ b1, const float* __restrict__ g1,
    const float* __restrict__ be1, const float* __restrict__ m1, const float* __restrict__ v1,
    const float* __restrict__ w2, const float* __restrict__ b2, const float* __restrict__ g2,
    const float* __restrict__ be2, const float* __restrict__ m2, const float* __restrict__ v2,
    const float* __restrict__ w3, const float* __restrict__ b3, const float* __restrict__ g3,
    const float* __restrict__ be3, const float* __restrict__ m3, const float* __restrict__ v3)
{
    int t = threadIdx.x;
    if (t < 64) {
        float s1 = g1[t] / sqrtf(v1[t] + 1e-5f);
        g_B[t] = (b1[t] - m1[t]) * s1 + be1[t];
        for (int c = 0; c < 3; c++) g_W1t[c * 64 + t] = w1[t * 3 + c] * s1;
        float s2 = g2[t] / sqrtf(v2[t] + 1e-5f);
        g_B[64 + t] = (b2[t] - m2[t]) * s2 + be2[t];
        for (int c = 0; c < 64; c++) g_W2t[c * 64 + t] = w2[t * 64 + c] * s2;
    }
    if (t < 128) {
        float s3 = g3[t] / sqrtf(v3[t] + 1e-5f);
        g_B[128 + t] = (b3[t] - m3[t]) * s3 + be3[t];
        for (int c = 0; c < 64; c++) g_W3t[c * 128 + t] = w3[t * 64 + c] * s3;
    }
}

// ---------------- FPS: Morton sort + 8-warp lazy loop, warp-coop updates ----------------
// sorted pos s -> group g = s>>5, slot j = s&31, shared addr a = (g<<5) | (j ^ (g&31))
// (XOR swizzle: conflict-free for both cooperative (fixed g, lane=j) and
//  per-lane serial (g = tid, fixed j across lanes) access patterns)
extern __shared__ float fps_sm[];

__device__ __forceinline__ unsigned spread3(unsigned v) {
    v = (v | (v << 4)) & 0x0C3u;
    v = (v | (v << 2)) & 0x249u;
    return v;
}

__global__ __launch_bounds__(256, 1) void fps_kernel(
    const float* __restrict__ xyz, float* __restrict__ newxyz)
{
    const int b = blockIdx.x;
    const float* P = xyz + (size_t)b * NPTS * 3;
    float* O = newxyz + (size_t)b * NPOINT * 3;
    const int tid = threadIdx.x;
    const int lane = tid & 31, wid = tid >> 5;

    float* sxs = fps_sm;                    // [8192] sorted-swizzled
    float* sys = sxs + NPTS;
    float* szs = sys + NPTS;
    float* dds = szs + NPTS;                // [8192]
    int*   ordt = (int*)(dds + NPTS);       // [8192] orig index per slot
    int*   hist = ordt + NPTS;              // [4096]
    unsigned short* inv = (unsigned short*)(hist + 4096);  // [8192] orig -> sorted pos

    __shared__ unsigned svv[2][8];
    __shared__ unsigned sii[2][8];
    __shared__ int wsums[8];

    // ---- pass A: keys + histogram ----
    for (int i = tid; i < 4096; i += 256) hist[i] = 0;
    __syncthreads();
    unsigned key[32];
#pragma unroll
    for (int k = 0; k < 32; k++) {
        int p = tid + 256 * k;
        float x = P[3 * p], y = P[3 * p + 1], z = P[3 * p + 2];
        int ix = min(15, max(0, (int)(x * 16.0f)));
        int iy = min(15, max(0, (int)(y * 16.0f)));
        int iz = min(15, max(0, (int)(z * 16.0f)));
        key[k] = spread3((unsigned)ix) | (spread3((unsigned)iy) << 1) | (spread3((unsigned)iz) << 2);
        atomicAdd(&hist[key[k]], 1);
    }
    __syncthreads();

    // ---- exclusive scan over 4096 bins (16/thread) ----
    int h[16]; int tsum = 0;
#pragma unroll
    for (int q = 0; q < 16; q++) { h[q] = hist[16 * tid + q]; tsum += h[q]; }
    int inc = tsum;
#pragma unroll
    for (int off = 1; off < 32; off <<= 1) {
        int n = __shfl_up_sync(FULLM, inc, off);
        if (lane >= off) inc += n;
    }
    if (lane == 31) wsums[wid] = inc;
    __syncthreads();
    if (tid == 0) {
        int run = 0;
#pragma unroll
        for (int w = 0; w < 8; w++) { int t = wsums[w]; wsums[w] = run; run += t; }
    }
    __syncthreads();
    {
        int run = wsums[wid] + (inc - tsum);
#pragma unroll
        for (int q = 0; q < 16; q++) { hist[16 * tid + q] = run; run += h[q]; }
    }
    __syncthreads();

    // ---- pass B: scatter into swizzled sorted layout ----
#pragma unroll
    for (int k = 0; k < 32; k++) {
        int orig = tid + 256 * k;
        float x = P[3 * orig], y = P[3 * orig + 1], z = P[3 * orig + 2];
        int s = atomicAdd(&hist[key[k]], 1);
        int g = s >> 5, j = s & 31;
        int a = (g << 5) | (j ^ (g & 31));
        sxs[a] = x; sys[a] = y; szs[a] = z;
        ordt[a] = orig;
        inv[orig] = (unsigned short)s;
    }
    __syncthreads();

    // ---- group cache init: thread t owns group t (32 points) ----
    float c0x = P[0], c0y = P[1], c0z = P[2];
    if (tid == 0) { O[0] = c0x; O[1] = c0y; O[2] = c0z; }

    const int g = tid;
    float bxl = 1e30f, bxh = -1e30f, byl = 1e30f, byh = -1e30f, bzl = 1e30f, bzh = -1e30f;
    float vth = -1.0f; unsigned bth = 0;
#pragma unroll 8
    for (int j = 0; j < 32; j++) {
        int a = (g << 5) | (j ^ lane);      // g & 31 == lane
        float x = sxs[a], y = sys[a], z = szs[a];
        bxl = fminf(bxl, x); bxh = fmaxf(bxh, x);
        byl = fminf(byl, y); byh = fmaxf(byh, y);
        bzl = fminf(bzl, z); bzh = fmaxf(bzh, z);
        float dx = __fadd_rn(x, -c0x), dy = __fadd_rn(y, -c0y), dz = __fadd_rn(z, -c0z);
        float dv = __fadd_rn(__fadd_rn(__fmul_rn(dx, dx), __fmul_rn(dy, dy)), __fmul_rn(dz, dz));
        dds[a] = dv;
        unsigned o = (unsigned)ordt[a];
        if (dv > vth) { vth = dv; bth = o; }
        else if (dv == vth) bth = min(bth, o);
    }
    const float bcx = (bxl + bxh) * 0.5f, bex = (bxh - bxl) * 0.5f;
    const float bcy = (byl + byh) * 0.5f, bey = (byh - byl) * 0.5f;
    const float bcz = (bzl + bzh) * 0.5f, bez = (bzh - bzl) * 0.5f;
    __syncthreads();

    float cx = c0x, cy = c0y, cz = c0z;

    for (int it = 1; it < NPOINT; ++it) {
        const int par = it & 1;

        // ---- conservative skip test (per-thread group bbox) ----
        float tx = fmaxf(fabsf(cx - bcx) - bex, 0.0f);
        float ty = fmaxf(fabsf(cy - bcy) - bey, 0.0f);
        float tz = fmaxf(fabsf(cz - bcz) - bez, 0.0f);
        float bound = tx * tx + ty * ty + tz * tz;
        bool fail = bound < vth * 1.0002f;
        unsigned need = __ballot_sync(FULLM, fail);

        if (__popc(need) >= 5) {
            // broad phase: each failing lane rescans its own group (lanes parallel)
            if (fail) {
                float v = -1.0f; unsigned bi = 0;
#pragma unroll 8
                for (int j = 0; j < 32; j++) {
                    int a = (g << 5) | (j ^ lane);
                    float dx = __fadd_rn(sxs[a], -cx);
                    float dy = __fadd_rn(sys[a], -cy);
                    float dz = __fadd_rn(szs[a], -cz);
                    float s = __fadd_rn(__fadd_rn(__fmul_rn(dx, dx), __fmul_rn(dy, dy)),
                                        __fmul_rn(dz, dz));
                    float dn = fminf(dds[a], s);
                    dds[a] = dn;
                    unsigned o = (unsigned)ordt[a];
                    if (dn > v) { v = dn; bi = o; }
                    else if (dn == v) bi = min(bi, o);
                }
                vth = v; bth = bi;
            }
            __syncwarp();
        } else {
            // sparse phase: warp cooperatively updates each failing group (1 pt/lane)
            while (need) {
                int k = __ffs(need) - 1; need &= need - 1;
                int gg = (wid << 5) | k;
                int a = (gg << 5) | (lane ^ k);      // gg & 31 == k
                float dx = __fadd_rn(sxs[a], -cx);
                float dy = __fadd_rn(sys[a], -cy);
                float dz = __fadd_rn(szs[a], -cz);
                float s = __fadd_rn(__fadd_rn(__fmul_rn(dx, dx), __fmul_rn(dy, dy)),
                                    __fmul_rn(dz, dz));
                float dn = fminf(dds[a], s);
                dds[a] = dn;
                unsigned kv = __float_as_uint(dn);   // d >= 0
                unsigned mx = __reduce_max_sync(FULLM, kv);
                unsigned cd = (kv == mx) ? (unsigned)ordt[a] : FULLM;
                unsigned mi = __reduce_min_sync(FULLM, cd);
                if (lane == k) { vth = __uint_as_float(mx); bth = mi; }
            }
        }

        // ---- warp argmax over 32 cached group maxima ----
        unsigned kv = __float_as_uint(vth);
        unsigned wm = __reduce_max_sync(FULLM, kv);
        unsigned cd = (kv == wm) ? bth : FULLM;
        unsigned wi = __reduce_min_sync(FULLM, cd);
        if (lane == 0) { svv[par][wid] = wm; sii[par][wid] = wi; }
        __syncthreads();

        // ---- block combine (8 warp results; every warp redundantly) ----
        unsigned kv8 = (lane < 8) ? svv[par][lane] : 0u;
        unsigned i8  = (lane < 8) ? sii[par][lane] : FULLM;
        unsigned m8  = __reduce_max_sync(FULLM, kv8);
        unsigned c8  = (kv8 == m8) ? i8 : FULLM;
        unsigned ci  = __reduce_min_sync(FULLM, c8);   // orig index of pick

        int s2 = (int)inv[ci];
        int g2 = s2 >> 5, j2 = s2 & 31;
        int a2 = (g2 << 5) | (j2 ^ (g2 & 31));
        cx = sxs[a2]; cy = sys[a2]; cz = szs[a2];
        if (tid == 0) { float* o = O + 3 * it; o[0] = cx; o[1] = cy; o[2] = cz; }
    }
}

// ---------------- fused ball-query + MLP + maxpool (unchanged) ----------------
extern __shared__ float fus_sm[];

__global__ __launch_bounds__(256) void fused_kernel(
    const float* __restrict__ xyz, const float* __restrict__ newxyz,
    float* __restrict__ out2)
{
    float* W2t   = fus_sm;
    float* W3t   = W2t + 64 * 64;
    float* W1t   = W3t + 64 * 128;
    float* Bsh   = W1t + 192;
    float* stage = Bsh + 256;
    int*   nb    = (int*)(stage + 128 * 8);

    const int tid = threadIdx.x;
    for (int i = tid; i < 64 * 64; i += 256)  W2t[i] = g_W2t[i];
    for (int i = tid; i < 64 * 128; i += 256) W3t[i] = g_W3t[i];
    if (tid < 192) W1t[tid] = g_W1t[tid];
    if (tid < 256) Bsh[tid] = g_B[tid];
    __syncthreads();

    const int w = tid >> 5, lane = tid & 31;
    const int b = blockIdx.x >> 8;
    const int m0 = (blockIdx.x & 255) * 8;
    const int m = m0 + w;

    const float* P = xyz + (size_t)b * NPTS * 3;
    const float* C = newxyz + ((size_t)b * NPOINT + m) * 3;
    const float cx = C[0], cy = C[1], cz = C[2];

    const float R2 = (float)(0.2 * 0.2);
    int* mynb = nb + w * 32;
    int cnt = 0;
    for (int base = 0; base < NPTS && cnt < NSAMPLE; base += 32) {
        int p = base + lane;
        float x = P[3 * p], y = P[3 * p + 1], z = P[3 * p + 2];
        float dx = __fadd_rn(x, -cx), dy = __fadd_rn(y, -cy), dz = __fadd_rn(z, -cz);
        float s = __fadd_rn(__fadd_rn(__fmul_rn(dx, dx), __fmul_rn(dy, dy)), __fmul_rn(dz, dz));
        bool in = (s <= R2);
        unsigned msk = __ballot_sync(FULLM, in);
        int pos = cnt + __popc(msk & ((1u << lane) - 1u));
        if (in && pos < NSAMPLE) mynb[pos] = p;
        cnt += __popc(msk);
    }
    __syncwarp();
    int src = (cnt >= NSAMPLE) ? lane : (lane % cnt);
    int gidx = mynb[src];

    float gx = P[3 * gidx] - cx, gy = P[3 * gidx + 1] - cy, gz = P[3 * gidx + 2] - cz;

    float h1[64];
#pragma unroll
    for (int o = 0; o < 64; o++) h1[o] = fmaf(gx, W1t[o], Bsh[o]);
#pragma unroll
    for (int o = 0; o < 64; o++) h1[o] = fmaf(gy, W1t[64 + o], h1[o]);
#pragma unroll
    for (int o = 0; o < 64; o++) h1[o] = fmaxf(fmaf(gz, W1t[128 + o], h1[o]), 0.0f);

    float h2[64];
#pragma unroll
    for (int o = 0; o < 64; o++) h2[o] = Bsh[64 + o];
#pragma unroll
    for (int c = 0; c < 64; c++) {
        float hc = h1[c];
        const float4* wr = (const float4*)(W2t + c * 64);
#pragma unroll
        for (int q = 0; q < 16; q++) {
            float4 wv = wr[q];
            h2[4 * q + 0] = fmaf(hc, wv.x, h2[4 * q + 0]);
            h2[4 * q + 1] = fmaf(hc, wv.y, h2[4 * q + 1]);
            h2[4 * q + 2] = fmaf(hc, wv.z, h2[4 * q + 2]);
            h2[4 * q + 3] = fmaf(hc, wv.w, h2[4 * q + 3]);
        }
    }
#pragma unroll
    for (int o = 0; o < 64; o++) h2[o] = fmaxf(h2[o], 0.0f);

#pragma unroll
    for (int half = 0; half < 2; half++) {
        float acc[64];
#pragma unroll
        for (int o = 0; o < 64; o++) acc[o] = Bsh[128 + half * 64 + o];
#pragma unroll
        for (int c = 0; c < 64; c++) {
            float hc = h2[c];
            const float4* wr = (const float4*)(W3t + c * 128 + half * 64);
#pragma unroll
            for (int q = 0; q < 16; q++) {
                float4 wv = wr[q];
                acc[4 * q + 0] = fmaf(hc, wv.x, acc[4 * q + 0]);
                acc[4 * q + 1] = fmaf(hc, wv.y, acc[4 * q + 1]);
                acc[4 * q + 2] = fmaf(hc, wv.z, acc[4 * q + 2]);
                acc[4 * q + 3] = fmaf(hc, wv.w, acc[4 * q + 3]);
            }
        }
#pragma unroll
        for (int o = 0; o < 64; o++) acc[o] = fmaxf(acc[o], 0.0f);
#pragma unroll
        for (int off = 16; off >= 1; off >>= 1) {
#pragma unroll
            for (int o = 0; o < 64; o++)
                acc[o] = fmaxf(acc[o], __shfl_down_sync(FULLM, acc[o], off));
        }
        if (lane == 0) {
#pragma unroll
            for (int o = 0; o < 64; o++) stage[(half * 64 + o) * 8 + w] = acc[o];
        }
    }
    __syncthreads();

    {
        int ch = tid >> 1, part = tid & 1;
        float4 v = ((const float4*)stage)[tid];
        *(float4*)(out2 + ((size_t)(b * 128 + ch)) * NPOINT + m0 + part * 4) = v;
    }
}

// ---------------- launch ----------------
extern "C" void kernel_launch(void* const* d_in, const int* in_sizes, int n_in,
                              void* d_out, int out_size)
{
    const float* xyz = (const float*)d_in[0];
    const float* w1 = (const float*)d_in[1];  const float* b1 = (const float*)d_in[2];
    const float* g1 = (const float*)d_in[3];  const float* be1 = (const float*)d_in[4];
    const float* m1 = (const float*)d_in[5];  const float* v1 = (const float*)d_in[6];
    const float* w2 = (const float*)d_in[7];  const float* b2 = (const float*)d_in[8];
    const float* g2 = (const float*)d_in[9];  const float* be2 = (const float*)d_in[10];
    const float* m2 = (const float*)d_in[11]; const float* v2 = (const float*)d_in[12];
    const float* w3 = (const float*)d_in[13]; const float* b3 = (const float*)d_in[14];
    const float* g3 = (const float*)d_in[15]; const float* be3 = (const float*)d_in[16];
    const float* m3 = (const float*)d_in[17]; const float* v3 = (const float*)d_in[18];

    float* out = (float*)d_out;
    float* newxyz = out;
    float* out2 = out + (size_t)BATCH * NPOINT * 3;

    // smem: sxs,sys,szs,dds (4*8192 f) + ordt (8192 i) + hist (4096 i) + inv (8192 u16)
    const int FPS_SMEM = (4 * NPTS + NPTS + 4096) * 4 + NPTS * 2;   // 196608
    cudaFuncSetAttribute(fps_kernel, cudaFuncAttributeMaxDynamicSharedMemorySize, FPS_SMEM);
    cudaFuncSetAttribute(fused_kernel, cudaFuncAttributeMaxDynamicSharedMemorySize, 57344);

    prep_kernel<<<1, 128>>>(w1, b1, g1, be1, m1, v1,
                            w2, b2, g2, be2, m2, v2,
                            w3, b3, g3, be3, m3, v3);
    fps_kernel<<<BATCH, 256, FPS_SMEM>>>(xyz, newxyz);
    fused_kernel<<<BATCH * (NPOINT / 8), 256, 56064>>>(xyz, newxyz, out2);
    (void)in_sizes; (void)n_in; (void)out_size;
}

// round 7
// speedup vs baseline: 9.9421x; 1.9869x over previous
#include <cuda_runtime.h>
#include <math.h>

#define BATCH   8
#define NPTS    8192
#define NPOINT  2048
#define NSAMPLE 32
#define FULLM   0xffffffffu

// ---------------- device scratch (no allocs allowed) ----------------
__device__ float g_W1t[3 * 64];
__device__ float g_W2t[64 * 64];
__device__ float g_W3t[64 * 128];
__device__ float g_B[256];

// ---------------- prep: fold BN into weights ----------------
__global__ void prep_kernel(
    const float* __restrict__ w1, const float* __restrict__ b1, const float* __restrict__ g1,
    const float* __restrict__ be1, const float* __restrict__ m1, const float* __restrict__ v1,
    const float* __restrict__ w2, const float* __restrict__ b2, const float* __restrict__ g2,
    const float* __restrict__ be2, const float* __restrict__ m2, const float* __restrict__ v2,
    const float* __restrict__ w3, const float* __restrict__ b3, const float* __restrict__ g3,
    const float* __restrict__ be3, const float* __restrict__ m3, const float* __restrict__ v3)
{
    int t = threadIdx.x;
    if (t < 64) {
        float s1 = g1[t] / sqrtf(v1[t] + 1e-5f);
        g_B[t] = (b1[t] - m1[t]) * s1 + be1[t];
        for (int c = 0; c < 3; c++) g_W1t[c * 64 + t] = w1[t * 3 + c] * s1;
        float s2 = g2[t] / sqrtf(v2[t] + 1e-5f);
        g_B[64 + t] = (b2[t] - m2[t]) * s2 + be2[t];
        for (int c = 0; c < 64; c++) g_W2t[c * 64 + t] = w2[t * 64 + c] * s2;
    }
    if (t < 128) {
        float s3 = g3[t] / sqrtf(v3[t] + 1e-5f);
        g_B[128 + t] = (b3[t] - m3[t]) * s3 + be3[t];
        for (int c = 0; c < 64; c++) g_W3t[c * 128 + t] = w3[t * 64 + c] * s3;
    }
}

// ---------------- FPS: 512 threads, 16 pts/thread (2x8-pt bboxes), lazy ----------------
extern __shared__ float fps_sm[];

__device__ __forceinline__ unsigned spread3(unsigned v) {
    v = (v | (v << 4)) & 0x0C3u;
    v = (v | (v << 2)) & 0x249u;
    return v;
}

__global__ __launch_bounds__(512, 1) void fps_kernel(
    const float* __restrict__ xyz, float* __restrict__ newxyz)
{
    const int b = blockIdx.x;
    const float* P = xyz + (size_t)b * NPTS * 3;
    float* O = newxyz + (size_t)b * NPOINT * 3;
    const int tid = threadIdx.x;
    const int lane = tid & 31, wid = tid >> 5;

    float* shx = fps_sm;                    // [8192] by original index
    float* shy = shx + NPTS;
    float* shz = shy + NPTS;
    int*   hist  = (int*)(shz + NPTS);      // [4096]
    int*   order = hist + 4096;             // [8192]

    __shared__ unsigned svv[2][16];
    __shared__ unsigned sii[2][16];
    __shared__ int wsums[16];

    // ---- pass A: load -> shared mirror (orig index) + Morton histogram ----
    for (int i = tid; i < 4096; i += 512) hist[i] = 0;
    __syncthreads();
    unsigned key[16];
#pragma unroll
    for (int k = 0; k < 16; k++) {
        int p = tid + 512 * k;
        float x = P[3 * p], y = P[3 * p + 1], z = P[3 * p + 2];
        shx[p] = x; shy[p] = y; shz[p] = z;
        int ix = min(15, max(0, (int)(x * 16.0f)));
        int iy = min(15, max(0, (int)(y * 16.0f)));
        int iz = min(15, max(0, (int)(z * 16.0f)));
        key[k] = spread3((unsigned)ix) | (spread3((unsigned)iy) << 1) | (spread3((unsigned)iz) << 2);
        atomicAdd(&hist[key[k]], 1);
    }
    __syncthreads();

    // ---- exclusive scan over 4096 bins (8/thread, 16 warps) ----
    int h[8]; int tsum = 0;
#pragma unroll
    for (int q = 0; q < 8; q++) { h[q] = hist[8 * tid + q]; tsum += h[q]; }
    int inc = tsum;
#pragma unroll
    for (int off = 1; off < 32; off <<= 1) {
        int n = __shfl_up_sync(FULLM, inc, off);
        if (lane >= off) inc += n;
    }
    if (lane == 31) wsums[wid] = inc;
    __syncthreads();
    if (tid == 0) {
        int run = 0;
#pragma unroll
        for (int w = 0; w < 16; w++) { int t = wsums[w]; wsums[w] = run; run += t; }
    }
    __syncthreads();
    {
        int run = wsums[wid] + (inc - tsum);
#pragma unroll
        for (int q = 0; q < 8; q++) { hist[8 * tid + q] = run; run += h[q]; }
    }
    __syncthreads();

    // ---- pass B: scatter orig indices into sorted order ----
#pragma unroll
    for (int k = 0; k < 16; k++) {
        int pos = atomicAdd(&hist[key[k]], 1);
        order[pos] = tid + 512 * k;
    }
    __syncthreads();

    // ---- gather my 16 sorted points; 2 halves with own bbox + cached argmax ----
    float cx = P[0], cy = P[1], cz = P[2];
    if (tid == 0) { O[0] = cx; O[1] = cy; O[2] = cz; }

    int orig[16];
    float d[16];
    float AxL = 1e30f, AxH = -1e30f, AyL = 1e30f, AyH = -1e30f, AzL = 1e30f, AzH = -1e30f;
    float BxL = 1e30f, BxH = -1e30f, ByL = 1e30f, ByH = -1e30f, BzL = 1e30f, BzH = -1e30f;
#pragma unroll
    for (int j = 0; j < 16; j++) {
        int o = order[16 * tid + j];
        orig[j] = o;
        float x = shx[o], y = shy[o], z = shz[o];
        if (j < 8) {
            AxL = fminf(AxL, x); AxH = fmaxf(AxH, x);
            AyL = fminf(AyL, y); AyH = fmaxf(AyH, y);
            AzL = fminf(AzL, z); AzH = fmaxf(AzH, z);
        } else {
            BxL = fminf(BxL, x); BxH = fmaxf(BxH, x);
            ByL = fminf(ByL, y); ByH = fmaxf(ByH, y);
            BzL = fminf(BzL, z); BzH = fmaxf(BzH, z);
        }
        float dx = __fadd_rn(x, -cx), dy = __fadd_rn(y, -cy), dz = __fadd_rn(z, -cz);
        d[j] = __fadd_rn(__fadd_rn(__fmul_rn(dx, dx), __fmul_rn(dy, dy)), __fmul_rn(dz, dz));
    }
    const float Acx = (AxL + AxH) * 0.5f, Aex = (AxH - AxL) * 0.5f;
    const float Acy = (AyL + AyH) * 0.5f, Aey = (AyH - AyL) * 0.5f;
    const float Acz = (AzL + AzH) * 0.5f, Aez = (AzH - AzL) * 0.5f;
    const float Bcx = (BxL + BxH) * 0.5f, Bex = (BxH - BxL) * 0.5f;
    const float Bcy = (ByL + ByH) * 0.5f, Bey = (ByH - ByL) * 0.5f;
    const float Bcz = (BzL + BzH) * 0.5f, Bez = (BzH - BzL) * 0.5f;

    // cached per-half argmax (max value, min orig index among ties)
    float vA, vB; unsigned iA, iB;
    {
        float v = d[0];
#pragma unroll
        for (int j = 1; j < 8; j++) v = fmaxf(v, d[j]);
        unsigned bi = FULLM;
#pragma unroll
        for (int j = 0; j < 8; j++) if (d[j] == v) bi = min(bi, (unsigned)orig[j]);
        vA = v; iA = bi;
        v = d[8];
#pragma unroll
        for (int j = 9; j < 16; j++) v = fmaxf(v, d[j]);
        bi = FULLM;
#pragma unroll
        for (int j = 8; j < 16; j++) if (d[j] == v) bi = min(bi, (unsigned)orig[j]);
        vB = v; iB = bi;
    }
    __syncthreads();

    for (int it = 1; it < NPOINT; ++it) {
        const int par = it & 1;

        // ---- conservative skip tests, one per half ----
        float tx = fmaxf(fabsf(cx - Acx) - Aex, 0.0f);
        float ty = fmaxf(fabsf(cy - Acy) - Aey, 0.0f);
        float tz = fmaxf(fabsf(cz - Acz) - Aez, 0.0f);
        if (tx * tx + ty * ty + tz * tz < vA * 1.0002f) {
#pragma unroll
            for (int j = 0; j < 8; j++) {
                int o = orig[j];
                float dx = __fadd_rn(shx[o], -cx);
                float dy = __fadd_rn(shy[o], -cy);
                float dz = __fadd_rn(shz[o], -cz);
                float s = __fadd_rn(__fadd_rn(__fmul_rn(dx, dx), __fmul_rn(dy, dy)),
                                    __fmul_rn(dz, dz));
                d[j] = fminf(d[j], s);
            }
            float v = d[0];
#pragma unroll
            for (int j = 1; j < 8; j++) v = fmaxf(v, d[j]);
            unsigned bi = FULLM;
#pragma unroll
            for (int j = 0; j < 8; j++) if (d[j] == v) bi = min(bi, (unsigned)orig[j]);
            vA = v; iA = bi;
        }
        tx = fmaxf(fabsf(cx - Bcx) - Bex, 0.0f);
        ty = fmaxf(fabsf(cy - Bcy) - Bey, 0.0f);
        tz = fmaxf(fabsf(cz - Bcz) - Bez, 0.0f);
        if (tx * tx + ty * ty + tz * tz < vB * 1.0002f) {
#pragma unroll
            for (int j = 8; j < 16; j++) {
                int o = orig[j];
                float dx = __fadd_rn(shx[o], -cx);
                float dy = __fadd_rn(shy[o], -cy);
                float dz = __fadd_rn(shz[o], -cz);
                float s = __fadd_rn(__fadd_rn(__fmul_rn(dx, dx), __fmul_rn(dy, dy)),
                                    __fmul_rn(dz, dz));
                d[j] = fminf(d[j], s);
            }
            float v = d[8];
#pragma unroll
            for (int j = 9; j < 16; j++) v = fmaxf(v, d[j]);
            unsigned bi = FULLM;
#pragma unroll
            for (int j = 8; j < 16; j++) if (d[j] == v) bi = min(bi, (unsigned)orig[j]);
            vB = v; iB = bi;
        }

        // ---- thread result (exact cross-half tie-break) ----
        float vth = fmaxf(vA, vB);
        unsigned bth = (vA > vB) ? iA : ((vB > vA) ? iB : min(iA, iB));

        // ---- warp argmax: reduce_max + ballot/shfl (fast path), redux_min on tie ----
        unsigned keyv = __float_as_uint(vth);       // d >= 0
        unsigned wmax = __reduce_max_sync(FULLM, keyv);
        unsigned eq = __ballot_sync(FULLM, keyv == wmax);
        unsigned wbi;
        if (__popc(eq) == 1) {
            wbi = __shfl_sync(FULLM, bth, __ffs(eq) - 1);
        } else {
            unsigned cand = (keyv == wmax) ? bth : FULLM;
            wbi = __reduce_min_sync(FULLM, cand);
        }
        if (lane == 0) { svv[par][wid] = wmax; sii[par][wid] = wbi; }
        __syncthreads();

        // ---- block combine over 16 warp results (every warp redundantly) ----
        unsigned kv16 = (lane < 16) ? svv[par][lane] : 0u;
        unsigned m16 = __reduce_max_sync(FULLM, kv16);
        unsigned eq2 = __ballot_sync(FULLM, kv16 == m16);
        unsigned ci;
        if (__popc(eq2) == 1) {
            ci = __shfl_sync(FULLM, (lane < 16) ? sii[par][lane] : FULLM, __ffs(eq2) - 1);
        } else {
            unsigned cand2 = (kv16 == m16) ? ((lane < 16) ? sii[par][lane] : FULLM) : FULLM;
            ci = __reduce_min_sync(FULLM, cand2);
        }

        cx = shx[ci]; cy = shy[ci]; cz = shz[ci];
        if (tid == 0) { float* o = O + 3 * it; o[0] = cx; o[1] = cy; o[2] = cz; }
    }
}

// ---------------- fused ball-query + MLP + maxpool (unchanged) ----------------
extern __shared__ float fus_sm[];

__global__ __launch_bounds__(256) void fused_kernel(
    const float* __restrict__ xyz, const float* __restrict__ newxyz,
    float* __restrict__ out2)
{
    float* W2t   = fus_sm;
    float* W3t   = W2t + 64 * 64;
    float* W1t   = W3t + 64 * 128;
    float* Bsh   = W1t + 192;
    float* stage = Bsh + 256;
    int*   nb    = (int*)(stage + 128 * 8);

    const int tid = threadIdx.x;
    for (int i = tid; i < 64 * 64; i += 256)  W2t[i] = g_W2t[i];
    for (int i = tid; i < 64 * 128; i += 256) W3t[i] = g_W3t[i];
    if (tid < 192) W1t[tid] = g_W1t[tid];
    if (tid < 256) Bsh[tid] = g_B[tid];
    __syncthreads();

    const int w = tid >> 5, lane = tid & 31;
    const int b = blockIdx.x >> 8;
    const int m0 = (blockIdx.x & 255) * 8;
    const int m = m0 + w;

    const float* P = xyz + (size_t)b * NPTS * 3;
    const float* C = newxyz + ((size_t)b * NPOINT + m) * 3;
    const float cx = C[0], cy = C[1], cz = C[2];

    const float R2 = (float)(0.2 * 0.2);
    int* mynb = nb + w * 32;
    int cnt = 0;
    for (int base = 0; base < NPTS && cnt < NSAMPLE; base += 32) {
        int p = base + lane;
        float x = P[3 * p], y = P[3 * p + 1], z = P[3 * p + 2];
        float dx = __fadd_rn(x, -cx), dy = __fadd_rn(y, -cy), dz = __fadd_rn(z, -cz);
        float s = __fadd_rn(__fadd_rn(__fmul_rn(dx, dx), __fmul_rn(dy, dy)), __fmul_rn(dz, dz));
        bool in = (s <= R2);
        unsigned msk = __ballot_sync(FULLM, in);
        int pos = cnt + __popc(msk & ((1u << lane) - 1u));
        if (in && pos < NSAMPLE) mynb[pos] = p;
        cnt += __popc(msk);
    }
    __syncwarp();
    int src = (cnt >= NSAMPLE) ? lane : (lane % cnt);
    int gidx = mynb[src];

    float gx = P[3 * gidx] - cx, gy = P[3 * gidx + 1] - cy, gz = P[3 * gidx + 2] - cz;

    float h1[64];
#pragma unroll
    for (int o = 0; o < 64; o++) h1[o] = fmaf(gx, W1t[o], Bsh[o]);
#pragma unroll
    for (int o = 0; o < 64; o++) h1[o] = fmaf(gy, W1t[64 + o], h1[o]);
#pragma unroll
    for (int o = 0; o < 64; o++) h1[o] = fmaxf(fmaf(gz, W1t[128 + o], h1[o]), 0.0f);

    float h2[64];
#pragma unroll
    for (int o = 0; o < 64; o++) h2[o] = Bsh[64 + o];
#pragma unroll
    for (int c = 0; c < 64; c++) {
        float hc = h1[c];
        const float4* wr = (const float4*)(W2t + c * 64);
#pragma unroll
        for (int q = 0; q < 16; q++) {
            float4 wv = wr[q];
            h2[4 * q + 0] = fmaf(hc, wv.x, h2[4 * q + 0]);
            h2[4 * q + 1] = fmaf(hc, wv.y, h2[4 * q + 1]);
            h2[4 * q + 2] = fmaf(hc, wv.z, h2[4 * q + 2]);
            h2[4 * q + 3] = fmaf(hc, wv.w, h2[4 * q + 3]);
        }
    }
#pragma unroll
    for (int o = 0; o < 64; o++) h2[o] = fmaxf(h2[o], 0.0f);

#pragma unroll
    for (int half = 0; half < 2; half++) {
        float acc[64];
#pragma unroll
        for (int o = 0; o < 64; o++) acc[o] = Bsh[128 + half * 64 + o];
#pragma unroll
        for (int c = 0; c < 64; c++) {
            float hc = h2[c];
            const float4* wr = (const float4*)(W3t + c * 128 + half * 64);
#pragma unroll
            for (int q = 0; q < 16; q++) {
                float4 wv = wr[q];
                acc[4 * q + 0] = fmaf(hc, wv.x, acc[4 * q + 0]);
                acc[4 * q + 1] = fmaf(hc, wv.y, acc[4 * q + 1]);
                acc[4 * q + 2] = fmaf(hc, wv.z, acc[4 * q + 2]);
                acc[4 * q + 3] = fmaf(hc, wv.w, acc[4 * q + 3]);
            }
        }
#pragma unroll
        for (int o = 0; o < 64; o++) acc[o] = fmaxf(acc[o], 0.0f);
#pragma unroll
        for (int off = 16; off >= 1; off >>= 1) {
#pragma unroll
            for (int o = 0; o < 64; o++)
                acc[o] = fmaxf(acc[o], __shfl_down_sync(FULLM, acc[o], off));
        }
        if (lane == 0) {
#pragma unroll
            for (int o = 0; o < 64; o++) stage[(half * 64 + o) * 8 + w] = acc[o];
        }
    }
    __syncthreads();

    {
        int ch = tid >> 1, part = tid & 1;
        float4 v = ((const float4*)stage)[tid];
        *(float4*)(out2 + ((size_t)(b * 128 + ch)) * NPOINT + m0 + part * 4) = v;
    }
}

// ---------------- launch ----------------
extern "C" void kernel_launch(void* const* d_in, const int* in_sizes, int n_in,
                              void* d_out, int out_size)
{
    const float* xyz = (const float*)d_in[0];
    const float* w1 = (const float*)d_in[1];  const float* b1 = (const float*)d_in[2];
    const float* g1 = (const float*)d_in[3];  const float* be1 = (const float*)d_in[4];
    const float* m1 = (const float*)d_in[5];  const float* v1 = (const float*)d_in[6];
    const float* w2 = (const float*)d_in[7];  const float* b2 = (const float*)d_in[8];
    const float* g2 = (const float*)d_in[9];  const float* be2 = (const float*)d_in[10];
    const float* m2 = (const float*)d_in[11]; const float* v2 = (const float*)d_in[12];
    const float* w3 = (const float*)d_in[13]; const float* b3 = (const float*)d_in[14];
    const float* g3 = (const float*)d_in[15]; const float* be3 = (const float*)d_in[16];
    const float* m3 = (const float*)d_in[17]; const float* v3 = (const float*)d_in[18];

    float* out = (float*)d_out;
    float* newxyz = out;
    float* out2 = out + (size_t)BATCH * NPOINT * 3;

    const int FPS_SMEM = (3 * NPTS + 4096 + NPTS) * 4;   // 147456 bytes
    cudaFuncSetAttribute(fps_kernel, cudaFuncAttributeMaxDynamicSharedMemorySize, FPS_SMEM);
    cudaFuncSetAttribute(fused_kernel, cudaFuncAttributeMaxDynamicSharedMemorySize, 57344);

    prep_kernel<<<1, 128>>>(w1, b1, g1, be1, m1, v1,
                            w2, b2, g2, be2, m2, v2,
                            w3, b3, g3, be3, m3, v3);
    fps_kernel<<<BATCH, 512, FPS_SMEM>>>(xyz, newxyz);
    fused_kernel<<<BATCH * (NPOINT / 8), 256, 56064>>>(xyz, newxyz, out2);
    (void)in_sizes; (void)n_in; (void)out_size;
}

// round 8
// speedup vs baseline: 11.1821x; 1.1247x over previous
#include <cuda_runtime.h>
#include <math.h>

#define BATCH   8
#define NPTS    8192
#define NPOINT  2048
#define NSAMPLE 32
#define FULLM   0xffffffffu

// ---------------- device scratch (no allocs allowed) ----------------
__device__ float g_W1t[3 * 64];
__device__ float g_W2t[64 * 64];
__device__ float g_W3t[64 * 128];
__device__ float g_B[256];

// ---------------- prep: fold BN into weights ----------------
__global__ void prep_kernel(
    const float* __restrict__ w1, const float* __restrict__ b1, const float* __restrict__ g1,
    const float* __restrict__ be1, const float* __restrict__ m1, const float* __restrict__ v1,
    const float* __restrict__ w2, const float* __restrict__ b2, const float* __restrict__ g2,
    const float* __restrict__ be2, const float* __restrict__ m2, const float* __restrict__ v2,
    const float* __restrict__ w3, const float* __restrict__ b3, const float* __restrict__ g3,
    const float* __restrict__ be3, const float* __restrict__ m3, const float* __restrict__ v3)
{
    int t = threadIdx.x;
    if (t < 64) {
        float s1 = g1[t] / sqrtf(v1[t] + 1e-5f);
        g_B[t] = (b1[t] - m1[t]) * s1 + be1[t];
        for (int c = 0; c < 3; c++) g_W1t[c * 64 + t] = w1[t * 3 + c] * s1;
        float s2 = g2[t] / sqrtf(v2[t] + 1e-5f);
        g_B[64 + t] = (b2[t] - m2[t]) * s2 + be2[t];
        for (int c = 0; c < 64; c++) g_W2t[c * 64 + t] = w2[t * 64 + c] * s2;
    }
    if (t < 128) {
        float s3 = g3[t] / sqrtf(v3[t] + 1e-5f);
        g_B[128 + t] = (b3[t] - m3[t]) * s3 + be3[t];
        for (int c = 0; c < 64; c++) g_W3t[c * 128 + t] = w3[t * 64 + c] * s3;
    }
}

// ---------------- FPS: 1024 threads, Morton-sorted lazy, REGISTER coords ----------------
extern __shared__ float fps_sm[];

__device__ __forceinline__ unsigned spread3(unsigned v) {
    v = (v | (v << 4)) & 0x0C3u;
    v = (v | (v << 2)) & 0x249u;
    return v;
}

__global__ __launch_bounds__(1024, 1) void fps_kernel(
    const float* __restrict__ xyz, float* __restrict__ newxyz)
{
    const int b = blockIdx.x;
    const float* P = xyz + (size_t)b * NPTS * 3;
    float* O = newxyz + (size_t)b * NPOINT * 3;
    const int tid = threadIdx.x;
    const int lane = tid & 31, wid = tid >> 5;

    float* shx = fps_sm;                    // [8192] by original index (pick lookup only)
    float* shy = shx + NPTS;
    float* shz = shy + NPTS;
    int*   hist  = (int*)(shz + NPTS);      // [4096]
    int*   order = hist + 4096;             // [8192]

    __shared__ unsigned svv[2][32];
    __shared__ unsigned sii[2][32];
    __shared__ int wsums[32];

    // ---- load, mirror to shared (orig index), Morton keys + histogram ----
    for (int i = tid; i < 4096; i += 1024) hist[i] = 0;
    __syncthreads();
    unsigned key[8];
#pragma unroll
    for (int k = 0; k < 8; k++) {
        int p = tid + 1024 * k;
        float x = P[3 * p], y = P[3 * p + 1], z = P[3 * p + 2];
        shx[p] = x; shy[p] = y; shz[p] = z;
        int ix = min(15, max(0, (int)(x * 16.0f)));
        int iy = min(15, max(0, (int)(y * 16.0f)));
        int iz = min(15, max(0, (int)(z * 16.0f)));
        key[k] = spread3((unsigned)ix) | (spread3((unsigned)iy) << 1) | (spread3((unsigned)iz) << 2);
        atomicAdd(&hist[key[k]], 1);
    }
    __syncthreads();

    // ---- exclusive scan over 4096 bins (4/thread) ----
    int h0 = hist[4 * tid], h1 = hist[4 * tid + 1], h2 = hist[4 * tid + 2], h3 = hist[4 * tid + 3];
    int tsum = h0 + h1 + h2 + h3;
    int inc = tsum;
#pragma unroll
    for (int off = 1; off < 32; off <<= 1) {
        int n = __shfl_up_sync(FULLM, inc, off);
        if (lane >= off) inc += n;
    }
    if (lane == 31) wsums[wid] = inc;
    __syncthreads();
    if (wid == 0) {
        int s = wsums[lane];
        int i2 = s;
#pragma unroll
        for (int off = 1; off < 32; off <<= 1) {
            int n = __shfl_up_sync(FULLM, i2, off);
            if (lane >= off) i2 += n;
        }
        wsums[lane] = i2 - s;
    }
    __syncthreads();
    {
        int run = wsums[wid] + (inc - tsum);
        hist[4 * tid] = run; run += h0;
        hist[4 * tid + 1] = run; run += h1;
        hist[4 * tid + 2] = run; run += h2;
        hist[4 * tid + 3] = run;
    }
    __syncthreads();

    // ---- scatter orig indices into sorted order ----
#pragma unroll
    for (int k = 0; k < 8; k++) {
        int pos = atomicAdd(&hist[key[k]], 1);
        order[pos] = tid + 1024 * k;
    }
    __syncthreads();

    // ---- gather my 8 sorted points into REGISTERS; bbox; init dists vs P[0] ----
    float cx = P[0], cy = P[1], cz = P[2];
    if (tid == 0) { O[0] = cx; O[1] = cy; O[2] = cz; }

    int   orig[8];
    float px[8], py[8], pz[8], d[8];
    float bxl = 1e30f, bxh = -1e30f, byl = 1e30f, byh = -1e30f, bzl = 1e30f, bzh = -1e30f;
#pragma unroll
    for (int j = 0; j < 8; j++) {
        int o = order[8 * tid + j];
        orig[j] = o;
        float x = shx[o], y = shy[o], z = shz[o];
        px[j] = x; py[j] = y; pz[j] = z;
        bxl = fminf(bxl, x); bxh = fmaxf(bxh, x);
        byl = fminf(byl, y); byh = fmaxf(byh, y);
        bzl = fminf(bzl, z); bzh = fmaxf(bzh, z);
        float dx = __fadd_rn(x, -cx), dy = __fadd_rn(y, -cy), dz = __fadd_rn(z, -cz);
        d[j] = __fadd_rn(__fadd_rn(__fmul_rn(dx, dx), __fmul_rn(dy, dy)), __fmul_rn(dz, dz));
    }
    const float bcx = (bxl + bxh) * 0.5f, bex = (bxh - bxl) * 0.5f;
    const float bcy = (byl + byh) * 0.5f, bey = (byh - byl) * 0.5f;
    const float bcz = (bzl + bzh) * 0.5f, bez = (bzh - bzl) * 0.5f;

    // cached per-thread argmax (max value, min orig index among ties)
    float vmax; unsigned bidx;
    {
        float v = d[0];
#pragma unroll
        for (int j = 1; j < 8; j++) v = fmaxf(v, d[j]);
        unsigned bi = FULLM;
#pragma unroll
        for (int j = 0; j < 8; j++) if (d[j] == v) bi = min(bi, (unsigned)orig[j]);
        vmax = v; bidx = bi;
    }

    for (int it = 1; it < NPOINT; ++it) {
        const int par = it & 1;

        // ---- conservative skip test ----
        float tx = fmaxf(fabsf(cx - bcx) - bex, 0.0f);
        float ty = fmaxf(fabsf(cy - bcy) - bey, 0.0f);
        float tz = fmaxf(fabsf(cz - bcz) - bez, 0.0f);
        float bound = tx * tx + ty * ty + tz * tz;
        if (bound < vmax * 1.0002f) {
            // ---- register-only exact update of my 8 points ----
#pragma unroll
            for (int j = 0; j < 8; j++) {
                float dx = __fadd_rn(px[j], -cx);
                float dy = __fadd_rn(py[j], -cy);
                float dz = __fadd_rn(pz[j], -cz);
                float s = __fadd_rn(__fadd_rn(__fmul_rn(dx, dx), __fmul_rn(dy, dy)),
                                    __fmul_rn(dz, dz));
                d[j] = fminf(d[j], s);
            }
            float v = d[0];
#pragma unroll
            for (int j = 1; j < 8; j++) v = fmaxf(v, d[j]);
            unsigned bi = FULLM;
#pragma unroll
            for (int j = 0; j < 8; j++) if (d[j] == v) bi = min(bi, (unsigned)orig[j]);
            vmax = v; bidx = bi;
        }

        // ---- warp argmax via redux (value max, then min index among ties) ----
        unsigned keyv = __float_as_uint(vmax);          // d >= 0
        unsigned wmax = __reduce_max_sync(FULLM, keyv);
        unsigned cand = (keyv == wmax) ? bidx : FULLM;
        unsigned wbi  = __reduce_min_sync(FULLM, cand);
        if (lane == 0) { svv[par][wid] = wmax; sii[par][wid] = wbi; }
        __syncthreads();

        // ---- block argmax: every warp redundantly reduces the 32 warp results ----
        unsigned k2 = svv[par][lane];
        unsigned i2 = sii[par][lane];
        unsigned m2 = __reduce_max_sync(FULLM, k2);
        unsigned c2 = (k2 == m2) ? i2 : FULLM;
        unsigned ci = __reduce_min_sync(FULLM, c2);

        cx = shx[ci]; cy = shy[ci]; cz = shz[ci];   // same addr all warps -> broadcast
        if (tid == 0) { float* o = O + 3 * it; o[0] = cx; o[1] = cy; o[2] = cz; }
    }
}

// ---------------- fused ball-query + MLP + maxpool (unchanged) ----------------
extern __shared__ float fus_sm[];

__global__ __launch_bounds__(256) void fused_kernel(
    const float* __restrict__ xyz, const float* __restrict__ newxyz,
    float* __restrict__ out2)
{
    float* W2t   = fus_sm;
    float* W3t   = W2t + 64 * 64;
    float* W1t   = W3t + 64 * 128;
    float* Bsh   = W1t + 192;
    float* stage = Bsh + 256;
    int*   nb    = (int*)(stage + 128 * 8);

    const int tid = threadIdx.x;
    for (int i = tid; i < 64 * 64; i += 256)  W2t[i] = g_W2t[i];
    for (int i = tid; i < 64 * 128; i += 256) W3t[i] = g_W3t[i];
    if (tid < 192) W1t[tid] = g_W1t[tid];
    if (tid < 256) Bsh[tid] = g_B[tid];
    __syncthreads();

    const int w = tid >> 5, lane = tid & 31;
    const int b = blockIdx.x >> 8;
    const int m0 = (blockIdx.x & 255) * 8;
    const int m = m0 + w;

    const float* P = xyz + (size_t)b * NPTS * 3;
    const float* C = newxyz + ((size_t)b * NPOINT + m) * 3;
    const float cx = C[0], cy = C[1], cz = C[2];

    const float R2 = (float)(0.2 * 0.2);
    int* mynb = nb + w * 32;
    int cnt = 0;
    for (int base = 0; base < NPTS && cnt < NSAMPLE; base += 32) {
        int p = base + lane;
        float x = P[3 * p], y = P[3 * p + 1], z = P[3 * p + 2];
        float dx = __fadd_rn(x, -cx), dy = __fadd_rn(y, -cy), dz = __fadd_rn(z, -cz);
        float s = __fadd_rn(__fadd_rn(__fmul_rn(dx, dx), __fmul_rn(dy, dy)), __fmul_rn(dz, dz));
        bool in = (s <= R2);
        unsigned msk = __ballot_sync(FULLM, in);
        int pos = cnt + __popc(msk & ((1u << lane) - 1u));
        if (in && pos < NSAMPLE) mynb[pos] = p;
        cnt += __popc(msk);
    }
    __syncwarp();
    int src = (cnt >= NSAMPLE) ? lane : (lane % cnt);
    int gidx = mynb[src];

    float gx = P[3 * gidx] - cx, gy = P[3 * gidx + 1] - cy, gz = P[3 * gidx + 2] - cz;

    float h1[64];
#pragma unroll
    for (int o = 0; o < 64; o++) h1[o] = fmaf(gx, W1t[o], Bsh[o]);
#pragma unroll
    for (int o = 0; o < 64; o++) h1[o] = fmaf(gy, W1t[64 + o], h1[o]);
#pragma unroll
    for (int o = 0; o < 64; o++) h1[o] = fmaxf(fmaf(gz, W1t[128 + o], h1[o]), 0.0f);

    float h2[64];
#pragma unroll
    for (int o = 0; o < 64; o++) h2[o] = Bsh[64 + o];
#pragma unroll
    for (int c = 0; c < 64; c++) {
        float hc = h1[c];
        const float4* wr = (const float4*)(W2t + c * 64);
#pragma unroll
        for (int q = 0; q < 16; q++) {
            float4 wv = wr[q];
            h2[4 * q + 0] = fmaf(hc, wv.x, h2[4 * q + 0]);
            h2[4 * q + 1] = fmaf(hc, wv.y, h2[4 * q + 1]);
            h2[4 * q + 2] = fmaf(hc, wv.z, h2[4 * q + 2]);
            h2[4 * q + 3] = fmaf(hc, wv.w, h2[4 * q + 3]);
        }
    }
#pragma unroll
    for (int o = 0; o < 64; o++) h2[o] = fmaxf(h2[o], 0.0f);

#pragma unroll
    for (int half = 0; half < 2; half++) {
        float acc[64];
#pragma unroll
        for (int o = 0; o < 64; o++) acc[o] = Bsh[128 + half * 64 + o];
#pragma unroll
        for (int c = 0; c < 64; c++) {
            float hc = h2[c];
            const float4* wr = (const float4*)(W3t + c * 128 + half * 64);
#pragma unroll
            for (int q = 0; q < 16; q++) {
                float4 wv = wr[q];
                acc[4 * q + 0] = fmaf(hc, wv.x, acc[4 * q + 0]);
                acc[4 * q + 1] = fmaf(hc, wv.y, acc[4 * q + 1]);
                acc[4 * q + 2] = fmaf(hc, wv.z, acc[4 * q + 2]);
                acc[4 * q + 3] = fmaf(hc, wv.w, acc[4 * q + 3]);
            }
        }
#pragma unroll
        for (int o = 0; o < 64; o++) acc[o] = fmaxf(acc[o], 0.0f);
#pragma unroll
        for (int off = 16; off >= 1; off >>= 1) {
#pragma unroll
            for (int o = 0; o < 64; o++)
                acc[o] = fmaxf(acc[o], __shfl_down_sync(FULLM, acc[o], off));
        }
        if (lane == 0) {
#pragma unroll
            for (int o = 0; o < 64; o++) stage[(half * 64 + o) * 8 + w] = acc[o];
        }
    }
    __syncthreads();

    {
        int ch = tid >> 1, part = tid & 1;
        float4 v = ((const float4*)stage)[tid];
        *(float4*)(out2 + ((size_t)(b * 128 + ch)) * NPOINT + m0 + part * 4) = v;
    }
}

// ---------------- launch ----------------
extern "C" void kernel_launch(void* const* d_in, const int* in_sizes, int n_in,
                              void* d_out, int out_size)
{
    const float* xyz = (const float*)d_in[0];
    const float* w1 = (const float*)d_in[1];  const float* b1 = (const float*)d_in[2];
    const float* g1 = (const float*)d_in[3];  const float* be1 = (const float*)d_in[4];
    const float* m1 = (const float*)d_in[5];  const float* v1 = (const float*)d_in[6];
    const float* w2 = (const float*)d_in[7];  const float* b2 = (const float*)d_in[8];
    const float* g2 = (const float*)d_in[9];  const float* be2 = (const float*)d_in[10];
    const float* m2 = (const float*)d_in[11]; const float* v2 = (const float*)d_in[12];
    const float* w3 = (const float*)d_in[13]; const float* b3 = (const float*)d_in[14];
    const float* g3 = (const float*)d_in[15]; const float* be3 = (const float*)d_in[16];
    const float* m3 = (const float*)d_in[17]; const float* v3 = (const float*)d_in[18];

    float* out = (float*)d_out;
    float* newxyz = out;
    float* out2 = out + (size_t)BATCH * NPOINT * 3;

    const int FPS_SMEM = (3 * NPTS + 4096 + NPTS) * 4;   // 147456 bytes
    cudaFuncSetAttribute(fps_kernel, cudaFuncAttributeMaxDynamicSharedMemorySize, FPS_SMEM);
    cudaFuncSetAttribute(fused_kernel, cudaFuncAttributeMaxDynamicSharedMemorySize, 57344);

    prep_kernel<<<1, 128>>>(w1, b1, g1, be1, m1, v1,
                            w2, b2, g2, be2, m2, v2,
                            w3, b3, g3, be3, m3, v3);
    fps_kernel<<<BATCH, 1024, FPS_SMEM>>>(xyz, newxyz);
    fused_kernel<<<BATCH * (NPOINT / 8), 256, 56064>>>(xyz, newxyz, out2);
    (void)in_sizes; (void)n_in; (void)out_size;
}